// round 6
// baseline (speedup 1.0000x reference)
#include <cuda_runtime.h>

// CRF loss: logZ - gold.  T=512, B=512, N=64.
// Exp-space forward, 2 warps x 2 software-interleaved chains per block.

#define TT 512
#define BB 512
#define NN 64
#define LOG2E 1.4426950408889634f
#define LN2F  0.6931471805599453f
#define STRIDE_F (BB * NN)

#define FWD_BLOCKS  256                  // 2 chains per 64-thread block
#define GOLD_BLOCKS 4096                 // (T*B)/64
#define TOT_BLOCKS  (FWD_BLOCKS + GOLD_BLOCKS)

typedef unsigned long long ull;

__device__ __align__(16) float g_EpT[NN * NN];   // exp(trans)^T : [j][i]
__device__ double   g_logZ;
__device__ double   g_gold;
__device__ unsigned g_done;

__device__ __forceinline__ float ex2f_(float x) {
    float y; asm("ex2.approx.ftz.f32 %0, %1;" : "=f"(y) : "f"(x)); return y;
}
__device__ __forceinline__ float lg2f_(float x) {
    float y; asm("lg2.approx.ftz.f32 %0, %1;" : "=f"(y) : "f"(x)); return y;
}
__device__ __forceinline__ void fma2_(ull& d, ull a, ull b) {
    asm("fma.rn.f32x2 %0, %1, %2, %0;" : "+l"(d) : "l"(a), "l"(b));
}
__device__ __forceinline__ ull add2_(ull a, ull b) {
    ull d; asm("add.rn.f32x2 %0, %1, %2;" : "=l"(d) : "l"(a), "l"(b));
    return d;
}
__device__ __forceinline__ float pairsum_(ull a) {
    unsigned lo, hi;
    asm("mov.b64 {%0, %1}, %2;" : "=r"(lo), "=r"(hi) : "l"(a));
    return __uint_as_float(lo) + __uint_as_float(hi);
}

// mask dtype: 0=int32, 1=float32, 2=byte  (row t=0 all-true since lengths>=1)
__device__ __forceinline__ int mask_kind(const void* maskp) {
    unsigned w0 = ((const unsigned*)maskp)[0];
    return (w0 == 1u) ? 0 : (w0 == 0x3F800000u ? 1 : 2);
}
__device__ __forceinline__ bool mask_at(const void* maskp, int kind, int idx) {
    if (kind == 0) return ((const int*)maskp)[idx] != 0;
    if (kind == 1) return ((const float*)maskp)[idx] != 0.0f;
    return ((const unsigned char*)maskp)[idx] != 0;
}

// ---------------- init ------------------------------------------------------
__global__ void k_init(const float* __restrict__ trans) {
    int tid = blockIdx.x * blockDim.x + threadIdx.x;
    if (tid < NN * NN) {
        int i = tid & (NN - 1);
        int j = tid >> 6;
        g_EpT[tid] = ex2f_(LOG2E * trans[i * NN + j]);
    }
    if (tid == 0) { g_logZ = 0.0; g_gold = 0.0; g_done = 0u; }
}

// ---------------- fused forward + gold + final ------------------------------
__global__ void __launch_bounds__(64, 1)
k_main(const float* __restrict__ emit,
       const float* __restrict__ trans,
       const float* __restrict__ strans,
       const float* __restrict__ etrans,
       const int*   __restrict__ target,
       const void*  __restrict__ maskp,
       float*       __restrict__ out) {
    __shared__ __align__(16) float pbuf[2][2][NN];  // [chain][buffer][j]
    __shared__ float sslot[2][2];                   // [chain][buffer]
    __shared__ float red[8];

    const int tid = threadIdx.x;

    if (blockIdx.x < FWD_BLOCKS) {
        const int w = tid >> 5;
        const int l = tid & 31;
        const int j = tid;
        const int b0 = 2 * blockIdx.x;
        const int b1 = b0 + 1;

        // both chain lengths from prefix mask (block-cooperative)
        const int kind = mask_kind(maskp);
        int c0 = 0, c1 = 0;
#pragma unroll
        for (int k = 0; k < 8; ++k) {
            int row = (tid + 64 * k) * BB;
            c0 += mask_at(maskp, kind, row + b0) ? 1 : 0;
            c1 += mask_at(maskp, kind, row + b1) ? 1 : 0;
        }
        c0 = __reduce_add_sync(0xffffffffu, c0);
        c1 = __reduce_add_sync(0xffffffffu, c1);
        if (l == 0) { red[2 * w] = (float)c0; red[2 * w + 1] = (float)c1; }
        __syncthreads();
        const int len0 = (int)red[0] + (int)red[2];
        const int len1 = (int)red[1] + (int)red[3];
        const int lenmax = len0 > len1 ? len0 : len1;

        // E column j, i-pair packed
        ull E[32];
        {
            const ull* ep = (const ull*)(g_EpT + j * NN);
#pragma unroll
            for (int k = 0; k < 32; ++k) E[k] = ep[k];
        }

        const float* ebA = emit + (size_t)b0 * NN + j;
        const float* ebB = emit + (size_t)b1 * NN + j;
        const float stj = strans[j];

        float A0 = LOG2E * (ebA[0] + stj);
        float A1 = LOG2E * (ebB[0] + stj);
        __syncthreads();
        if (tid == 0) { red[0] = A0; red[1] = A1; }
        __syncthreads();
        float PF0 = ex2f_(A0 - red[0]);
        float PF1 = ex2f_(A1 - red[1]);
        float mlog0 = red[0], mlog1 = red[1];
        float u0 = 1.0f, d0 = 0.0f;
        float u1 = 1.0f, d1 = 0.0f;

        pbuf[0][1][j] = PF0;
        pbuf[1][1][j] = PF1;
        __syncthreads();

        // raw emit rings, depth 4 (load now, convert 4 iterations later)
        float rA0, rA1, rA2, rA3, rB0, rB1, rB2, rB3;
#define LD0(tt) ebA[(size_t)((tt) < len0 ? (tt) : (len0 - 1)) * STRIDE_F]
#define LD1(tt) ebB[(size_t)((tt) < len1 ? (tt) : (len1 - 1)) * STRIDE_F]
        rA0 = LD0(1); rA1 = LD0(2); rA2 = LD0(3); rA3 = LD0(4);
        rB0 = LD1(1); rB1 = LD1(2); rB2 = LD1(3); rB3 = LD1(4);

        int t = 1;
#define MATVEC(SVAR, CH, BI) {                                                \
        const ulonglong2* pb = (const ulonglong2*)pbuf[CH][BI];               \
        ull a0 = 0, a1 = 0, a2 = 0, a3 = 0;                                   \
        _Pragma("unroll")                                                     \
        for (int m = 0; m < 16; m += 2) {                                     \
            ulonglong2 q = pb[m];                                             \
            ulonglong2 r = pb[m + 1];                                         \
            fma2_(a0, q.x, E[2 * m]);     fma2_(a1, q.y, E[2 * m + 1]);       \
            fma2_(a2, r.x, E[2 * m + 2]); fma2_(a3, r.y, E[2 * m + 3]);       \
        }                                                                     \
        SVAR = pairsum_(add2_(add2_(a0, a1), add2_(a2, a3)));                 \
    }
#define SCALEUP(UV, DV, V0) {                                                 \
        int ex = (int)((__float_as_uint(V0) >> 23) & 0xFF);                   \
        int dd = ex - 127;                                                    \
        if (ex == 0 || ex == 255) dd = 0;                                     \
        if (dd > 120) dd = 120; if (dd < -120) dd = -120;                     \
        UV = __uint_as_float((unsigned)(127 - dd) << 23);                     \
        DV = (float)dd;                                                       \
    }
#define ITER(RA, RB, BI, BO) {                                                \
        float gA = ex2f_(LOG2E * RA);                                         \
        float gB = ex2f_(LOG2E * RB);                                         \
        RA = LD0(t + 4);                                                      \
        RB = LD1(t + 4);                                                      \
        float sA, sB;                                                         \
        MATVEC(sA, 0, BI)                                                     \
        MATVEC(sB, 1, BI)                                                     \
        if (t < len0) {                                                       \
            float pn = sA * (gA * u0);                                        \
            pbuf[0][BO][j] = pn;                                              \
            if (j == 0) sslot[0][BO] = sA;                                    \
            PF0 = pn; mlog0 += d0;                                            \
        }                                                                     \
        if (t < len1) {                                                       \
            float pn = sB * (gB * u1);                                        \
            pbuf[1][BO][j] = pn;                                              \
            if (j == 0) sslot[1][BO] = sB;                                    \
            PF1 = pn; mlog1 += d1;                                            \
        }                                                                     \
        __syncthreads();                                                      \
        if (t < len0) { float v = sslot[0][BO]; SCALEUP(u0, d0, v) }          \
        if (t < len1) { float v = sslot[1][BO]; SCALEUP(u1, d1, v) }          \
        ++t; }

        while (t + 3 < lenmax) {          // t ≡ 1 (mod 4) at loop head
            ITER(rA0, rB0, 1, 0)
            ITER(rA1, rB1, 0, 1)
            ITER(rA2, rB2, 1, 0)
            ITER(rA3, rB3, 0, 1)
        }
        while (t < lenmax) {              // ≤3 remainder iterations
            float ra = LD0(t), rb = LD1(t);
            int bi = t & 1, bo = bi ^ 1;
            float gA = ex2f_(LOG2E * ra);
            float gB = ex2f_(LOG2E * rb);
            float sA, sB;
            MATVEC(sA, 0, bi)
            MATVEC(sB, 1, bi)
            if (t < len0) {
                float pn = sA * (gA * u0);
                pbuf[0][bo][j] = pn;
                if (j == 0) sslot[0][bo] = sA;
                PF0 = pn; mlog0 += d0;
            }
            if (t < len1) {
                float pn = sB * (gB * u1);
                pbuf[1][bo][j] = pn;
                if (j == 0) sslot[1][bo] = sB;
                PF1 = pn; mlog1 += d1;
            }
            __syncthreads();
            if (t < len0) { float v = sslot[0][bo]; SCALEUP(u0, d0, v) }
            if (t < len1) { float v = sslot[1][bo]; SCALEUP(u1, d1, v) }
            ++t;
        }

        // logZ for both chains: alpha(log2) = lg2(PF) + mlog
        const float etj = LOG2E * etrans[j];
#pragma unroll
        for (int c = 0; c < 2; ++c) {
            float G = (c == 0 ? lg2f_(PF0) + mlog0 : lg2f_(PF1) + mlog1) + etj;
            float m2 = G;
#pragma unroll
            for (int o = 16; o; o >>= 1)
                m2 = fmaxf(m2, __shfl_xor_sync(0xffffffffu, m2, o));
            float s = ex2f_(G - m2);
#pragma unroll
            for (int o = 16; o; o >>= 1)
                s += __shfl_xor_sync(0xffffffffu, s, o);
            __syncthreads();
            if (l == 0) { red[w] = m2; red[2 + w] = s; }
            __syncthreads();
            if (tid == 0) {
                float ma = fmaxf(red[0], red[1]);
                float ss = red[2] * ex2f_(red[0] - ma) + red[3] * ex2f_(red[1] - ma);
                atomicAdd(&g_logZ, (double)(LN2F * (ma + lg2f_(ss))));
            }
        }
    } else {
        // ======== gold path score ========
        int idx = (blockIdx.x - FWD_BLOCKS) * 64 + tid;   // = t*BB + b
        int t = idx >> 9;
        int kind = mask_kind(maskp);
        float c = 0.0f;
        if (mask_at(maskp, kind, idx)) {
            int tg = target[idx];
            c = emit[(size_t)idx * NN + tg];
            if (t > 0) c += trans[target[idx - BB] * NN + tg];
            else       c += strans[tg];
            bool mnext = (t < TT - 1) && mask_at(maskp, kind, idx + BB);
            if (!mnext) c += etrans[tg];
        }
#pragma unroll
        for (int o = 16; o; o >>= 1) c += __shfl_xor_sync(0xffffffffu, c, o);
        if ((tid & 31) == 0) atomicAdd(&g_gold, (double)c);
    }

    // ======== last block writes the result ========
    __syncthreads();
    if (tid == 0) {
        __threadfence();
        if (atomicAdd(&g_done, 1u) == TOT_BLOCKS - 1) {
            double lz = atomicAdd(&g_logZ, 0.0);
            double gd = atomicAdd(&g_gold, 0.0);
            out[0] = (float)(lz - gd);
        }
    }
}

extern "C" void kernel_launch(void* const* d_in, const int* in_sizes, int n_in,
                              void* d_out, int out_size) {
    const float* emit   = (const float*)d_in[0];
    const float* trans  = (const float*)d_in[1];
    const float* strans = (const float*)d_in[2];
    const float* etrans = (const float*)d_in[3];
    const int*   target = (const int*)d_in[4];
    const void*  mask   = d_in[5];
    (void)in_sizes; (void)n_in; (void)out_size;

    k_init<<<16, 256>>>(trans);
    k_main<<<TOT_BLOCKS, 64>>>(emit, trans, strans, etrans, target, mask,
                               (float*)d_out);
}

// round 7
// speedup vs baseline: 1.5989x; 1.5989x over previous
#include <cuda_runtime.h>

// CRF loss: logZ - gold.  T=512, B=512, N=64.
// Exp-space forward. 4 independent chains per 256-thread block (64 thr each),
// named-barrier sync per chain, power-of-2 renorm every 4 steps.

#define TT 512
#define BB 512
#define NN 64
#define LOG2E 1.4426950408889634f
#define LN2F  0.6931471805599453f
#define STRIDE_F (BB * NN)

#define FWD_BLOCKS  128                  // 4 chains per 256-thread block
#define GOLD_BLOCKS 1024                 // (T*B)/256
#define TOT_BLOCKS  (FWD_BLOCKS + GOLD_BLOCKS)

typedef unsigned long long ull;

__device__ __align__(16) float g_EpT[NN * NN];   // exp(trans)^T : [j][i]
__device__ double   g_logZ;
__device__ double   g_gold;
__device__ unsigned g_done;

__device__ __forceinline__ float ex2f_(float x) {
    float y; asm("ex2.approx.ftz.f32 %0, %1;" : "=f"(y) : "f"(x)); return y;
}
__device__ __forceinline__ float lg2f_(float x) {
    float y; asm("lg2.approx.ftz.f32 %0, %1;" : "=f"(y) : "f"(x)); return y;
}
__device__ __forceinline__ void fma2_(ull& d, ull a, ull b) {
    asm("fma.rn.f32x2 %0, %1, %2, %0;" : "+l"(d) : "l"(a), "l"(b));
}
__device__ __forceinline__ ull add2_(ull a, ull b) {
    ull d; asm("add.rn.f32x2 %0, %1, %2;" : "=l"(d) : "l"(a), "l"(b));
    return d;
}
__device__ __forceinline__ float pairsum_(ull a) {
    unsigned lo, hi;
    asm("mov.b64 {%0, %1}, %2;" : "=r"(lo), "=r"(hi) : "l"(a));
    return __uint_as_float(lo) + __uint_as_float(hi);
}

// mask dtype: 0=int32, 1=float32, 2=byte  (row t=0 all-true since lengths>=1)
__device__ __forceinline__ int mask_kind(const void* maskp) {
    unsigned w0 = ((const unsigned*)maskp)[0];
    return (w0 == 1u) ? 0 : (w0 == 0x3F800000u ? 1 : 2);
}
__device__ __forceinline__ bool mask_at(const void* maskp, int kind, int idx) {
    if (kind == 0) return ((const int*)maskp)[idx] != 0;
    if (kind == 1) return ((const float*)maskp)[idx] != 0.0f;
    return ((const unsigned char*)maskp)[idx] != 0;
}

// ---------------- init ------------------------------------------------------
__global__ void k_init(const float* __restrict__ trans) {
    int tid = blockIdx.x * blockDim.x + threadIdx.x;
    if (tid < NN * NN) {
        int i = tid & (NN - 1);
        int j = tid >> 6;
        g_EpT[tid] = ex2f_(LOG2E * trans[i * NN + j]);
    }
    if (tid == 0) { g_logZ = 0.0; g_gold = 0.0; g_done = 0u; }
}

// ---------------- fused forward + gold + final ------------------------------
__global__ void __launch_bounds__(256, 1)
k_main(const float* __restrict__ emit,
       const float* __restrict__ trans,
       const float* __restrict__ strans,
       const float* __restrict__ etrans,
       const int*   __restrict__ target,
       const void*  __restrict__ maskp,
       float*       __restrict__ out) {
    __shared__ __align__(16) float pbuf[4][2][NN];  // [chain][buffer][j]
    __shared__ float sslot[4];                      // [chain] raw-sum sample
    __shared__ float red[4][4];                     // [chain] reduce slots

    const int tid = threadIdx.x;

    if (blockIdx.x < FWD_BLOCKS) {
        const int c  = tid >> 6;          // chain 0..3 (warps 2c, 2c+1)
        const int jt = tid & 63;          // state column j within chain
        const int w  = jt >> 5;           // warp-in-chain 0/1
        const int l  = tid & 31;
        const int b  = blockIdx.x * 4 + c;

        // per-chain sync: named barrier c+1, 64 threads
#define CBAR() asm volatile("bar.sync %0, %1;" :: "r"(c + 1), "r"(64) : "memory")

        // chain length from prefix mask
        const int kind = mask_kind(maskp);
        int cnt = 0;
#pragma unroll
        for (int k = 0; k < 8; ++k)
            cnt += mask_at(maskp, kind, (jt + 64 * k) * BB + b) ? 1 : 0;
        cnt = __reduce_add_sync(0xffffffffu, cnt);
        if (l == 0) red[c][w] = (float)cnt;
        CBAR();
        const int len = (int)red[c][0] + (int)red[c][1];

        // E column jt, i-pair packed: 32 x f32x2 registers
        ull E[32];
        {
            const ull* ep = (const ull*)(g_EpT + jt * NN);
#pragma unroll
            for (int k = 0; k < 32; ++k) E[k] = ep[k];
        }

        const float* eb = emit + (size_t)b * NN + jt;

        float A = LOG2E * (eb[0] + strans[jt]);
        if (jt == 0) red[c][2] = A;
        CBAR();
        const float M0 = red[c][2];
        float PF = ex2f_(A - M0);
        float mlog = M0;
        float u = 1.0f, dcur = 0.0f;

        pbuf[c][1][jt] = PF;
        CBAR();

        // raw emit ring, depth 4
        float r0, r1, r2, r3;
#define LDE(tt) eb[(size_t)((tt) < len ? (tt) : (len - 1)) * STRIDE_F]
        r0 = LDE(1); r1 = LDE(2); r2 = LDE(3); r3 = LDE(4);

        int t = 1;
        // STS_S: this step samples s into sslot (pre-bar)
        // TAIL:  0 = none, 1 = SCALEUP from sslot (post-bar), 2 = reset u,d
#define BODY(RR, BI, BO, STS_S, TAIL) {                                       \
        mlog += dcur;                                                         \
        float g = ex2f_(LOG2E * RR);                                          \
        RR = LDE(t + 4);                                                      \
        const ulonglong2* pb = (const ulonglong2*)pbuf[c][BI];                \
        ull a0 = 0, a1 = 0, a2 = 0, a3 = 0;                                   \
        _Pragma("unroll")                                                     \
        for (int m = 0; m < 16; m += 2) {                                     \
            ulonglong2 q = pb[m];                                             \
            ulonglong2 r = pb[m + 1];                                         \
            fma2_(a0, q.x, E[2 * m]);     fma2_(a1, q.y, E[2 * m + 1]);       \
            fma2_(a2, r.x, E[2 * m + 2]); fma2_(a3, r.y, E[2 * m + 3]);       \
        }                                                                     \
        float s = pairsum_(add2_(add2_(a0, a1), add2_(a2, a3)));              \
        float pn = s * (g * u);                                               \
        pbuf[c][BO][jt] = pn;                                                 \
        if (STS_S && jt == 0) sslot[c] = s;                                   \
        CBAR();                                                               \
        if (TAIL == 1) {                                                      \
            float v0 = sslot[c];                                              \
            int ex = (int)((__float_as_uint(v0) >> 23) & 0xFF);               \
            int dd = ex - 127;                                                \
            if (ex == 0 || ex == 255) dd = 0;                                 \
            if (dd > 120) dd = 120; if (dd < -120) dd = -120;                 \
            u = __uint_as_float((unsigned)(127 - dd) << 23);                  \
            dcur = (float)dd;                                                 \
        } else if (TAIL == 2) { u = 1.0f; dcur = 0.0f; }                      \
        PF = pn;                                                              \
        ++t; }

        while (t + 3 < len) {             // t ≡ 1 (mod 4) at loop head
            BODY(r0, 1, 0, 0, 0)          // t≡1
            BODY(r1, 0, 1, 0, 0)          // t≡2
            BODY(r2, 1, 0, 1, 1)          // t≡3: sample s, set scale
            BODY(r3, 0, 1, 0, 2)          // t≡0: apply scale, reset
        }
        while (t < len) {                 // ≤3 remainder steps, no renorm
            float rr = LDE(t);
            int bi = t & 1, bo = bi ^ 1;
            float g = ex2f_(LOG2E * rr);
            const ulonglong2* pb = (const ulonglong2*)pbuf[c][bi];
            ull a0 = 0, a1 = 0, a2 = 0, a3 = 0;
#pragma unroll
            for (int m = 0; m < 16; m += 2) {
                ulonglong2 q = pb[m];
                ulonglong2 r = pb[m + 1];
                fma2_(a0, q.x, E[2 * m]);     fma2_(a1, q.y, E[2 * m + 1]);
                fma2_(a2, r.x, E[2 * m + 2]); fma2_(a3, r.y, E[2 * m + 3]);
            }
            float s = pairsum_(add2_(add2_(a0, a1), add2_(a2, a3)));
            float pn = s * g;             // u == 1 here
            pbuf[c][bo][jt] = pn;
            CBAR();
            PF = pn;
            ++t;
        }

        // logZ_b = ln LSE_j(alpha_j + etrans_j),  alpha(log2) = lg2(PF)+mlog
        float G = lg2f_(PF) + mlog + LOG2E * etrans[jt];
        float m2 = G;
#pragma unroll
        for (int o = 16; o; o >>= 1) m2 = fmaxf(m2, __shfl_xor_sync(0xffffffffu, m2, o));
        float s = ex2f_(G - m2);
#pragma unroll
        for (int o = 16; o; o >>= 1) s += __shfl_xor_sync(0xffffffffu, s, o);
        CBAR();
        if (l == 0) { red[c][w] = m2; red[c][2 + w] = s; }
        CBAR();
        if (jt == 0) {
            float ma = fmaxf(red[c][0], red[c][1]);
            float ss = red[c][2] * ex2f_(red[c][0] - ma)
                     + red[c][3] * ex2f_(red[c][1] - ma);
            atomicAdd(&g_logZ, (double)(LN2F * (ma + lg2f_(ss))));
        }
    } else {
        // ======== gold path score ========
        int idx = (blockIdx.x - FWD_BLOCKS) * 256 + tid;   // = t*BB + b
        int t = idx >> 9;
        int kind = mask_kind(maskp);
        float c = 0.0f;
        if (mask_at(maskp, kind, idx)) {
            int tg = target[idx];
            c = emit[(size_t)idx * NN + tg];
            if (t > 0) c += trans[target[idx - BB] * NN + tg];
            else       c += strans[tg];
            bool mnext = (t < TT - 1) && mask_at(maskp, kind, idx + BB);
            if (!mnext) c += etrans[tg];
        }
#pragma unroll
        for (int o = 16; o; o >>= 1) c += __shfl_xor_sync(0xffffffffu, c, o);
        if ((tid & 31) == 0) atomicAdd(&g_gold, (double)c);
    }

    // ======== last block writes the result ========
    __syncthreads();
    if (tid == 0) {
        __threadfence();
        if (atomicAdd(&g_done, 1u) == TOT_BLOCKS - 1) {
            double lz = atomicAdd(&g_logZ, 0.0);
            double gd = atomicAdd(&g_gold, 0.0);
            out[0] = (float)(lz - gd);
        }
    }
}

extern "C" void kernel_launch(void* const* d_in, const int* in_sizes, int n_in,
                              void* d_out, int out_size) {
    const float* emit   = (const float*)d_in[0];
    const float* trans  = (const float*)d_in[1];
    const float* strans = (const float*)d_in[2];
    const float* etrans = (const float*)d_in[3];
    const int*   target = (const int*)d_in[4];
    const void*  mask   = d_in[5];
    (void)in_sizes; (void)n_in; (void)out_size;

    k_init<<<16, 256>>>(trans);
    k_main<<<TOT_BLOCKS, 256>>>(emit, trans, strans, etrans, target, mask,
                                (float*)d_out);
}